// round 3
// baseline (speedup 1.0000x reference)
#include <cuda_runtime.h>

#define H     128
#define MAXN  50000
#define MAXE  640000
#define NC    384            // [A | T | C] packed projection columns

// ---- scratch (static device memory; no allocations anywhere) ----
__device__ __align__(16) float g_Wcat[H * NC];      // 192 KB: [Wa | Wb | Wu1] as [128 x 384]
__device__ __align__(16) float g_v[H];              // W_msg row 256 (weight column)
__device__ __align__(16) float g_P[MAXN * NC];      // 76.8 MB: per-node [A | T | C]
__device__ __align__(16) int   g_keys[MAXN * H];    // 25.6 MB: encoded running max

#define KMIN ((int)0x80000000)

__device__ __forceinline__ int encf(float x) {
    int i = __float_as_int(x);
    return i >= 0 ? i : (i ^ 0x7FFFFFFF);   // order-preserving float->int
}
__device__ __forceinline__ float decf(int k) {
    int i = k >= 0 ? k : (k ^ 0x7FFFFFFF);
    return __int_as_float(i);
}

// ---------------------------------------------------------------------------
// Pack Wcat = [Wa | Wb | Wu1] (128 x 384) and v (128) from W_msg / W_upd.
// ---------------------------------------------------------------------------
__global__ void pack_kernel(const float* __restrict__ Wmsg,
                            const float* __restrict__ Wupd) {
    int idx = blockIdx.x * blockDim.x + threadIdx.x;
    if (idx < H) g_v[idx] = Wmsg[256 * H + idx];
    if (idx < H * NC) {
        int k = idx / NC, j = idx % NC;
        float val;
        if (j < H)            val = Wmsg[k * H + j];             // Wa
        else if (j < 2 * H)   val = Wmsg[(H + k) * H + (j - H)]; // Wb
        else                  val = Wupd[k * H + (j - 2 * H)];   // Wu1
        g_Wcat[idx] = val;
    }
}

// ---------------------------------------------------------------------------
// Initialize max keys to the encoded identity (INT_MIN).
// ---------------------------------------------------------------------------
__global__ void init_keys(int total4) {
    int4 v = make_int4(KMIN, KMIN, KMIN, KMIN);
    int4* p = reinterpret_cast<int4*>(g_keys);
    int stride = gridDim.x * blockDim.x;
    for (int i = blockIdx.x * blockDim.x + threadIdx.x; i < total4; i += stride)
        p[i] = v;
}

// ---------------------------------------------------------------------------
// GEMM1: P[M,384] = z[M,128] @ Wcat[128,384]; add b_msg to the T columns.
// 64x64 tile, BK=16, 256 threads, 4x4 microtile.
// ---------------------------------------------------------------------------
__global__ void gemm1_kernel(const float* __restrict__ z,
                             const float* __restrict__ bmsg, int M) {
    __shared__ float As[16][64];
    __shared__ float Bs[16][64];
    const int bm = blockIdx.x * 64, bn = blockIdx.y * 64;
    const int tid = threadIdx.x;
    const int tx = tid & 15, ty = tid >> 4;
    const int ar = tid >> 2, ac = (tid & 3) * 4;   // A loader: row 0..63, col base
    const int br = tid >> 4, bc = (tid & 15) * 4;  // B loader: row 0..15, col base
    float acc[4][4] = {};

    for (int k0 = 0; k0 < H; k0 += 16) {
        float4 av = make_float4(0.f, 0.f, 0.f, 0.f);
        if (bm + ar < M)
            av = *reinterpret_cast<const float4*>(z + (bm + ar) * H + k0 + ac);
        As[ac + 0][ar] = av.x; As[ac + 1][ar] = av.y;
        As[ac + 2][ar] = av.z; As[ac + 3][ar] = av.w;

        float4 bv = *reinterpret_cast<const float4*>(g_Wcat + (k0 + br) * NC + bn + bc);
        *reinterpret_cast<float4*>(&Bs[br][bc]) = bv;
        __syncthreads();

        #pragma unroll
        for (int kk = 0; kk < 16; kk++) {
            float a[4], b[4];
            #pragma unroll
            for (int i = 0; i < 4; i++) a[i] = As[kk][ty * 4 + i];
            #pragma unroll
            for (int j = 0; j < 4; j++) b[j] = Bs[kk][tx * 4 + j];
            #pragma unroll
            for (int i = 0; i < 4; i++)
                #pragma unroll
                for (int j = 0; j < 4; j++)
                    acc[i][j] += a[i] * b[j];
        }
        __syncthreads();
    }

    #pragma unroll
    for (int i = 0; i < 4; i++) {
        int row = bm + ty * 4 + i;
        if (row >= M) continue;
        #pragma unroll
        for (int j = 0; j < 4; j++) {
            int col = bn + tx * 4 + j;
            float v = acc[i][j];
            if (col >= H && col < 2 * H) v += bmsg[col - H];   // fold b_msg into T
            g_P[row * NC + col] = v;
        }
    }
}

// ---------------------------------------------------------------------------
// Edge kernel: one warp per edge. c = A[src] + w*v.
// Racy read-filter (__ldcg) then atomicMax into keys[dst]. The read only
// filters; atomicMax remains the sole commit point, so results are exact.
// ---------------------------------------------------------------------------
__global__ void edge_kernel(const int* __restrict__ src,
                            const int* __restrict__ dst,
                            const float* __restrict__ w, int E) {
    int gw = (blockIdx.x * blockDim.x + threadIdx.x) >> 5;
    int lane = threadIdx.x & 31;
    if (gw >= E) return;
    int s = __ldg(src + gw);
    int d = __ldg(dst + gw);
    float wt = __ldg(w + gw);

    float4 a  = *reinterpret_cast<const float4*>(g_P + s * NC + lane * 4);
    float4 vv = *reinterpret_cast<const float4*>(g_v + lane * 4);
    int k0 = encf(fmaf(wt, vv.x, a.x));
    int k1 = encf(fmaf(wt, vv.y, a.y));
    int k2 = encf(fmaf(wt, vv.z, a.z));
    int k3 = encf(fmaf(wt, vv.w, a.w));

    int* kp = g_keys + d * H + lane * 4;
    int4 cur = __ldcg(reinterpret_cast<const int4*>(kp));
    if (cur.x < k0) atomicMax(kp + 0, k0);
    if (cur.y < k1) atomicMax(kp + 1, k1);
    if (cur.z < k2) atomicMax(kp + 2, k2);
    if (cur.w < k3) atomicMax(kp + 3, k3);
}

// ---------------------------------------------------------------------------
// GEMM2: out[M,128] = agg[M,128] @ Wu2[128,128] + C + b_upd
// agg decoded on the fly in the A-tile loader: key==KMIN -> 0 else dec(key)+T.
// ---------------------------------------------------------------------------
__global__ void gemm2_kernel(const float* __restrict__ Wupd,
                             const float* __restrict__ bupd,
                             float* __restrict__ out, int M) {
    __shared__ float As[16][64];
    __shared__ float Bs[16][64];
    const int bm = blockIdx.x * 64, bn = blockIdx.y * 64;
    const int tid = threadIdx.x;
    const int tx = tid & 15, ty = tid >> 4;
    const int ar = tid >> 2, ac = (tid & 3) * 4;
    const int br = tid >> 4, bc = (tid & 15) * 4;
    float acc[4][4] = {};

    for (int k0 = 0; k0 < H; k0 += 16) {
        float4 a = make_float4(0.f, 0.f, 0.f, 0.f);
        int row = bm + ar;
        if (row < M) {
            int4   kv = *reinterpret_cast<const int4*>(g_keys + row * H + k0 + ac);
            float4 t4 = *reinterpret_cast<const float4*>(g_P + row * NC + H + k0 + ac);
            a.x = (kv.x == KMIN) ? 0.f : decf(kv.x) + t4.x;
            a.y = (kv.y == KMIN) ? 0.f : decf(kv.y) + t4.y;
            a.z = (kv.z == KMIN) ? 0.f : decf(kv.z) + t4.z;
            a.w = (kv.w == KMIN) ? 0.f : decf(kv.w) + t4.w;
        }
        As[ac + 0][ar] = a.x; As[ac + 1][ar] = a.y;
        As[ac + 2][ar] = a.z; As[ac + 3][ar] = a.w;

        // Wu2 = W_upd rows 128..255
        float4 bv = *reinterpret_cast<const float4*>(Wupd + (H + k0 + br) * H + bn + bc);
        *reinterpret_cast<float4*>(&Bs[br][bc]) = bv;
        __syncthreads();

        #pragma unroll
        for (int kk = 0; kk < 16; kk++) {
            float a_[4], b_[4];
            #pragma unroll
            for (int i = 0; i < 4; i++) a_[i] = As[kk][ty * 4 + i];
            #pragma unroll
            for (int j = 0; j < 4; j++) b_[j] = Bs[kk][tx * 4 + j];
            #pragma unroll
            for (int i = 0; i < 4; i++)
                #pragma unroll
                for (int j = 0; j < 4; j++)
                    acc[i][j] += a_[i] * b_[j];
        }
        __syncthreads();
    }

    #pragma unroll
    for (int i = 0; i < 4; i++) {
        int row = bm + ty * 4 + i;
        if (row >= M) continue;
        #pragma unroll
        for (int j = 0; j < 4; j++) {
            int col = bn + tx * 4 + j;
            out[row * H + col] = acc[i][j] + g_P[row * NC + 2 * H + col] + bupd[col];
        }
    }
}

// ---------------------------------------------------------------------------
extern "C" void kernel_launch(void* const* d_in, const int* in_sizes, int n_in,
                              void* d_out, int out_size) {
    const float* z    = (const float*)d_in[0];
    const int*   src  = (const int*)  d_in[1];
    const int*   dst  = (const int*)  d_in[2];
    const float* w    = (const float*)d_in[3];
    const float* Wmsg = (const float*)d_in[4];
    const float* bmsg = (const float*)d_in[5];
    const float* Wupd = (const float*)d_in[6];
    const float* bupd = (const float*)d_in[7];
    float* out = (float*)d_out;

    int n = in_sizes[0] / H;     // 50000
    int E = in_sizes[1];         // 640000

    pack_kernel<<<(H * NC + 255) / 256, 256>>>(Wmsg, Wupd);
    init_keys<<<256, 256>>>(n * H / 4);
    gemm1_kernel<<<dim3((n + 63) / 64, NC / 64), 256>>>(z, bmsg, n);
    edge_kernel<<<(E * 32 + 255) / 256, 256>>>(src, dst, w, E);
    gemm2_kernel<<<dim3((n + 63) / 64, H / 64), 256>>>(Wupd, bupd, out, n);
}

// round 4
// speedup vs baseline: 1.0550x; 1.0550x over previous
#include <cuda_runtime.h>

#define H     128
#define MAXN  50000
#define NC    384            // [A | T | C] packed projection columns

// ---- scratch (static device memory; no allocations anywhere) ----
__device__ __align__(16) float g_Wcat[H * NC];      // 192 KB: [Wa | Wb | Wu1] as [128 x 384]
__device__ __align__(16) float g_v[H];              // W_msg row 256 (weight column)
__device__ __align__(16) float g_P[MAXN * NC];      // 76.8 MB: per-node [A | T | C]
__device__ __align__(16) int   g_keys[MAXN * H];    // 25.6 MB: encoded running max

#define KMIN ((int)0x80000000)

__device__ __forceinline__ int encf(float x) {
    int i = __float_as_int(x);
    return i >= 0 ? i : (i ^ 0x7FFFFFFF);   // order-preserving float->int
}
__device__ __forceinline__ float decf(int k) {
    int i = k >= 0 ? k : (k ^ 0x7FFFFFFF);
    return __int_as_float(i);
}

// ---------------------------------------------------------------------------
// Pack Wcat = [Wa | Wb | Wu1] (128 x 384) and v (128) from W_msg / W_upd.
// ---------------------------------------------------------------------------
__global__ void pack_kernel(const float* __restrict__ Wmsg,
                            const float* __restrict__ Wupd) {
    int idx = blockIdx.x * blockDim.x + threadIdx.x;
    if (idx < H) g_v[idx] = Wmsg[256 * H + idx];
    if (idx < H * NC) {
        int k = idx / NC, j = idx % NC;
        float val;
        if (j < H)            val = Wmsg[k * H + j];             // Wa
        else if (j < 2 * H)   val = Wmsg[(H + k) * H + (j - H)]; // Wb
        else                  val = Wupd[k * H + (j - 2 * H)];   // Wu1
        g_Wcat[idx] = val;
    }
}

// ---------------------------------------------------------------------------
// Initialize max keys to the encoded identity (INT_MIN).
// ---------------------------------------------------------------------------
__global__ void init_keys(int total4) {
    int4 v = make_int4(KMIN, KMIN, KMIN, KMIN);
    int4* p = reinterpret_cast<int4*>(g_keys);
    int stride = gridDim.x * blockDim.x;
    for (int i = blockIdx.x * blockDim.x + threadIdx.x; i < total4; i += stride)
        p[i] = v;
}

// ---------------------------------------------------------------------------
// GEMM1: P[M,384] = z[M,128] @ Wcat[128,384]; add b_msg to the T columns.
// 128x128 tile, BK=8, 256 threads, 8x8 microtile (split 4+4 layout).
// ---------------------------------------------------------------------------
__global__ __launch_bounds__(256, 2)
void gemm1_kernel(const float* __restrict__ z,
                  const float* __restrict__ bmsg, int M) {
    __shared__ float As[8][128];
    __shared__ float Bs[8][128];
    const int bm = blockIdx.x * 128, bn = blockIdx.y * 128;
    const int tid = threadIdx.x;
    const int tx = tid & 15, ty = tid >> 4;
    const int arow = tid >> 1, acol = (tid & 1) * 4;   // A loader: 128 rows x 8 cols
    const int brow = tid >> 5, bcol = (tid & 31) * 4;  // B loader: 8 rows x 128 cols
    float acc[8][8] = {};

    for (int k0 = 0; k0 < H; k0 += 8) {
        float4 av = make_float4(0.f, 0.f, 0.f, 0.f);
        if (bm + arow < M)
            av = *reinterpret_cast<const float4*>(z + (bm + arow) * H + k0 + acol);
        As[acol + 0][arow] = av.x; As[acol + 1][arow] = av.y;
        As[acol + 2][arow] = av.z; As[acol + 3][arow] = av.w;

        float4 bv = *reinterpret_cast<const float4*>(g_Wcat + (k0 + brow) * NC + bn + bcol);
        *reinterpret_cast<float4*>(&Bs[brow][bcol]) = bv;
        __syncthreads();

        #pragma unroll
        for (int kk = 0; kk < 8; kk++) {
            float4 a0 = *reinterpret_cast<const float4*>(&As[kk][ty * 4]);
            float4 a1 = *reinterpret_cast<const float4*>(&As[kk][64 + ty * 4]);
            float4 b0 = *reinterpret_cast<const float4*>(&Bs[kk][tx * 4]);
            float4 b1 = *reinterpret_cast<const float4*>(&Bs[kk][64 + tx * 4]);
            float a[8] = {a0.x, a0.y, a0.z, a0.w, a1.x, a1.y, a1.z, a1.w};
            float b[8] = {b0.x, b0.y, b0.z, b0.w, b1.x, b1.y, b1.z, b1.w};
            #pragma unroll
            for (int i = 0; i < 8; i++)
                #pragma unroll
                for (int j = 0; j < 8; j++)
                    acc[i][j] = fmaf(a[i], b[j], acc[i][j]);
        }
        __syncthreads();
    }

    #pragma unroll
    for (int i = 0; i < 8; i++) {
        int row = bm + ((i < 4) ? (ty * 4 + i) : (64 + ty * 4 + i - 4));
        if (row >= M) continue;
        #pragma unroll
        for (int j = 0; j < 8; j++) {
            int col = bn + ((j < 4) ? (tx * 4 + j) : (64 + tx * 4 + j - 4));
            float v = acc[i][j];
            if (col >= H && col < 2 * H) v += bmsg[col - H];   // fold b_msg into T
            g_P[row * NC + col] = v;
        }
    }
}

// ---------------------------------------------------------------------------
// Edge kernel: one warp per edge. c = A[src] + w*v.
// Racy read-filter (__ldcg) then atomicMax into keys[dst]. The read only
// filters; atomicMax remains the sole commit point, so results are exact.
// ---------------------------------------------------------------------------
__global__ void edge_kernel(const int* __restrict__ src,
                            const int* __restrict__ dst,
                            const float* __restrict__ w, int E) {
    int gw = (blockIdx.x * blockDim.x + threadIdx.x) >> 5;
    int lane = threadIdx.x & 31;
    if (gw >= E) return;
    int s = __ldg(src + gw);
    int d = __ldg(dst + gw);
    float wt = __ldg(w + gw);

    float4 a  = *reinterpret_cast<const float4*>(g_P + s * NC + lane * 4);
    float4 vv = *reinterpret_cast<const float4*>(g_v + lane * 4);
    int k0 = encf(fmaf(wt, vv.x, a.x));
    int k1 = encf(fmaf(wt, vv.y, a.y));
    int k2 = encf(fmaf(wt, vv.z, a.z));
    int k3 = encf(fmaf(wt, vv.w, a.w));

    int* kp = g_keys + d * H + lane * 4;
    int4 cur = __ldcg(reinterpret_cast<const int4*>(kp));
    if (cur.x < k0) atomicMax(kp + 0, k0);
    if (cur.y < k1) atomicMax(kp + 1, k1);
    if (cur.z < k2) atomicMax(kp + 2, k2);
    if (cur.w < k3) atomicMax(kp + 3, k3);
}

// ---------------------------------------------------------------------------
// GEMM2: out[M,128] = agg[M,128] @ Wu2[128,128] + C + b_upd
// agg decoded on the fly in the A-tile loader: key==KMIN -> 0 else dec(key)+T.
// 128x128 tile, BK=8, 256 threads, 8x8 microtile.
// ---------------------------------------------------------------------------
__global__ __launch_bounds__(256, 2)
void gemm2_kernel(const float* __restrict__ Wupd,
                  const float* __restrict__ bupd,
                  float* __restrict__ out, int M) {
    __shared__ float As[8][128];
    __shared__ float Bs[8][128];
    const int bm = blockIdx.x * 128, bn = 0;
    const int tid = threadIdx.x;
    const int tx = tid & 15, ty = tid >> 4;
    const int arow = tid >> 1, acol = (tid & 1) * 4;
    const int brow = tid >> 5, bcol = (tid & 31) * 4;
    float acc[8][8] = {};

    for (int k0 = 0; k0 < H; k0 += 8) {
        float4 a = make_float4(0.f, 0.f, 0.f, 0.f);
        int row = bm + arow;
        if (row < M) {
            int4   kv = *reinterpret_cast<const int4*>(g_keys + row * H + k0 + acol);
            float4 t4 = *reinterpret_cast<const float4*>(g_P + row * NC + H + k0 + acol);
            a.x = (kv.x == KMIN) ? 0.f : decf(kv.x) + t4.x;
            a.y = (kv.y == KMIN) ? 0.f : decf(kv.y) + t4.y;
            a.z = (kv.z == KMIN) ? 0.f : decf(kv.z) + t4.z;
            a.w = (kv.w == KMIN) ? 0.f : decf(kv.w) + t4.w;
        }
        As[acol + 0][arow] = a.x; As[acol + 1][arow] = a.y;
        As[acol + 2][arow] = a.z; As[acol + 3][arow] = a.w;

        // Wu2 = W_upd rows 128..255
        float4 bv = *reinterpret_cast<const float4*>(Wupd + (H + k0 + brow) * H + bn + bcol);
        *reinterpret_cast<float4*>(&Bs[brow][bcol]) = bv;
        __syncthreads();

        #pragma unroll
        for (int kk = 0; kk < 8; kk++) {
            float4 a0 = *reinterpret_cast<const float4*>(&As[kk][ty * 4]);
            float4 a1 = *reinterpret_cast<const float4*>(&As[kk][64 + ty * 4]);
            float4 b0 = *reinterpret_cast<const float4*>(&Bs[kk][tx * 4]);
            float4 b1 = *reinterpret_cast<const float4*>(&Bs[kk][64 + tx * 4]);
            float a_[8] = {a0.x, a0.y, a0.z, a0.w, a1.x, a1.y, a1.z, a1.w};
            float b_[8] = {b0.x, b0.y, b0.z, b0.w, b1.x, b1.y, b1.z, b1.w};
            #pragma unroll
            for (int i = 0; i < 8; i++)
                #pragma unroll
                for (int j = 0; j < 8; j++)
                    acc[i][j] = fmaf(a_[i], b_[j], acc[i][j]);
        }
        __syncthreads();
    }

    #pragma unroll
    for (int i = 0; i < 8; i++) {
        int row = bm + ((i < 4) ? (ty * 4 + i) : (64 + ty * 4 + i - 4));
        if (row >= M) continue;
        #pragma unroll
        for (int j = 0; j < 8; j++) {
            int col = bn + ((j < 4) ? (tx * 4 + j) : (64 + tx * 4 + j - 4));
            out[row * H + col] = acc[i][j] + g_P[row * NC + 2 * H + col] + bupd[col];
        }
    }
}

// ---------------------------------------------------------------------------
extern "C" void kernel_launch(void* const* d_in, const int* in_sizes, int n_in,
                              void* d_out, int out_size) {
    const float* z    = (const float*)d_in[0];
    const int*   src  = (const int*)  d_in[1];
    const int*   dst  = (const int*)  d_in[2];
    const float* w    = (const float*)d_in[3];
    const float* Wmsg = (const float*)d_in[4];
    const float* bmsg = (const float*)d_in[5];
    const float* Wupd = (const float*)d_in[6];
    const float* bupd = (const float*)d_in[7];
    float* out = (float*)d_out;

    int n = in_sizes[0] / H;     // 50000
    int E = in_sizes[1];         // 640000

    pack_kernel<<<(H * NC + 255) / 256, 256>>>(Wmsg, Wupd);
    init_keys<<<256, 256>>>(n * H / 4);
    gemm1_kernel<<<dim3((n + 127) / 128, NC / 128), 256>>>(z, bmsg, n);
    edge_kernel<<<(E * 32 + 255) / 256, 256>>>(src, dst, w, E);
    gemm2_kernel<<<(n + 127) / 128, 256>>>(Wupd, bupd, out, n);
}

// round 5
// speedup vs baseline: 1.2152x; 1.1518x over previous
#include <cuda_runtime.h>

#define H     128
#define MAXN  50000
#define NC    384            // [A | T | C] packed projection columns
#define EPW   4              // edges per warp

// ---- scratch (static device memory; no allocations anywhere) ----
__device__ __align__(16) float g_Wcat[H * NC];      // 192 KB: [Wa | Wb | Wu1] as [128 x 384]
__device__ __align__(16) float g_v[H];              // W_msg row 256 (weight column)
__device__ __align__(16) float g_P[MAXN * NC];      // 76.8 MB: per-node [A | T | C]
__device__ __align__(16) int   g_keys[MAXN * H];    // 25.6 MB: encoded running max

#define KMIN ((int)0x80000000)

__device__ __forceinline__ int encf(float x) {
    int i = __float_as_int(x);
    return i >= 0 ? i : (i ^ 0x7FFFFFFF);   // order-preserving float->int
}
__device__ __forceinline__ float decf(int k) {
    int i = k >= 0 ? k : (k ^ 0x7FFFFFFF);
    return __int_as_float(i);
}

// ---------------------------------------------------------------------------
// Pack Wcat = [Wa | Wb | Wu1] (128 x 384) and v (128) from W_msg / W_upd.
// ---------------------------------------------------------------------------
__global__ void pack_kernel(const float* __restrict__ Wmsg,
                            const float* __restrict__ Wupd) {
    int idx = blockIdx.x * blockDim.x + threadIdx.x;
    if (idx < H) g_v[idx] = Wmsg[256 * H + idx];
    if (idx < H * NC) {
        int k = idx / NC, j = idx % NC;
        float val;
        if (j < H)            val = Wmsg[k * H + j];             // Wa
        else if (j < 2 * H)   val = Wmsg[(H + k) * H + (j - H)]; // Wb
        else                  val = Wupd[k * H + (j - 2 * H)];   // Wu1
        g_Wcat[idx] = val;
    }
}

// ---------------------------------------------------------------------------
// Initialize max keys to the encoded identity (INT_MIN).
// ---------------------------------------------------------------------------
__global__ void init_keys(int total4) {
    int4 v = make_int4(KMIN, KMIN, KMIN, KMIN);
    int4* p = reinterpret_cast<int4*>(g_keys);
    int stride = gridDim.x * blockDim.x;
    for (int i = blockIdx.x * blockDim.x + threadIdx.x; i < total4; i += stride)
        p[i] = v;
}

// ---------------------------------------------------------------------------
// GEMM1: P[M,384] = z[M,128] @ Wcat[128,384]; add b_msg to the T columns.
// 128x128 tile, BK=8, 256 threads, 8x8 microtile, double-buffered smem.
// ---------------------------------------------------------------------------
__global__ __launch_bounds__(256, 2)
void gemm1_kernel(const float* __restrict__ z,
                  const float* __restrict__ bmsg, int M) {
    __shared__ float As[2][8][128];
    __shared__ float Bs[2][8][128];
    const int bm = blockIdx.x * 128, bn = blockIdx.y * 128;
    const int tid = threadIdx.x;
    const int tx = tid & 15, ty = tid >> 4;
    const int arow = tid >> 1, acol = (tid & 1) * 4;   // A loader: 128 rows x 8 cols
    const int brow = tid >> 5, bcol = (tid & 31) * 4;  // B loader: 8 rows x 128 cols
    const bool arow_ok = (bm + arow < M);
    float acc[8][8] = {};

    // prologue: stage 0
    {
        float4 av = make_float4(0.f, 0.f, 0.f, 0.f);
        if (arow_ok)
            av = *reinterpret_cast<const float4*>(z + (bm + arow) * H + acol);
        As[0][acol + 0][arow] = av.x; As[0][acol + 1][arow] = av.y;
        As[0][acol + 2][arow] = av.z; As[0][acol + 3][arow] = av.w;
        float4 bv = *reinterpret_cast<const float4*>(g_Wcat + brow * NC + bn + bcol);
        *reinterpret_cast<float4*>(&Bs[0][brow][bcol]) = bv;
    }
    __syncthreads();

    #pragma unroll 2
    for (int it = 0; it < 16; it++) {
        const int cur = it & 1;
        float4 av2 = make_float4(0.f, 0.f, 0.f, 0.f), bv2;
        if (it < 15) {
            int k0 = (it + 1) * 8;
            if (arow_ok)
                av2 = *reinterpret_cast<const float4*>(z + (bm + arow) * H + k0 + acol);
            bv2 = *reinterpret_cast<const float4*>(g_Wcat + (k0 + brow) * NC + bn + bcol);
        }

        #pragma unroll
        for (int kk = 0; kk < 8; kk++) {
            float4 a0 = *reinterpret_cast<const float4*>(&As[cur][kk][ty * 4]);
            float4 a1 = *reinterpret_cast<const float4*>(&As[cur][kk][64 + ty * 4]);
            float4 b0 = *reinterpret_cast<const float4*>(&Bs[cur][kk][tx * 4]);
            float4 b1 = *reinterpret_cast<const float4*>(&Bs[cur][kk][64 + tx * 4]);
            float a[8] = {a0.x, a0.y, a0.z, a0.w, a1.x, a1.y, a1.z, a1.w};
            float b[8] = {b0.x, b0.y, b0.z, b0.w, b1.x, b1.y, b1.z, b1.w};
            #pragma unroll
            for (int i = 0; i < 8; i++)
                #pragma unroll
                for (int j = 0; j < 8; j++)
                    acc[i][j] = fmaf(a[i], b[j], acc[i][j]);
        }

        if (it < 15) {
            const int nxt = cur ^ 1;
            As[nxt][acol + 0][arow] = av2.x; As[nxt][acol + 1][arow] = av2.y;
            As[nxt][acol + 2][arow] = av2.z; As[nxt][acol + 3][arow] = av2.w;
            *reinterpret_cast<float4*>(&Bs[nxt][brow][bcol]) = bv2;
        }
        __syncthreads();
    }

    #pragma unroll
    for (int i = 0; i < 8; i++) {
        int row = bm + ((i < 4) ? (ty * 4 + i) : (64 + ty * 4 + i - 4));
        if (row >= M) continue;
        #pragma unroll
        for (int j = 0; j < 8; j++) {
            int col = bn + ((j < 4) ? (tx * 4 + j) : (64 + tx * 4 + j - 4));
            float v = acc[i][j];
            if (col >= H && col < 2 * H) v += bmsg[col - H];   // fold b_msg into T
            g_P[row * NC + col] = v;
        }
    }
}

// ---------------------------------------------------------------------------
// Edge kernel: EPW edges per warp for memory-level parallelism.
// c = A[src] + w*v ; racy __ldcg filter then atomicMax (exact: the atomic is
// the only commit point). 8 independent 16B loads in flight per lane.
// ---------------------------------------------------------------------------
__global__ void edge_kernel(const int* __restrict__ src,
                            const int* __restrict__ dst,
                            const float* __restrict__ w, int E) {
    int warp = (blockIdx.x * blockDim.x + threadIdx.x) >> 5;
    int lane = threadIdx.x & 31;
    int e0 = warp * EPW;
    if (e0 >= E) return;

    float4 vv = *reinterpret_cast<const float4*>(g_v + lane * 4);

    int s[EPW], d[EPW]; float wt[EPW];
    #pragma unroll
    for (int j = 0; j < EPW; j++) {
        int e = (e0 + j < E) ? e0 + j : e0;
        s[j]  = __ldg(src + e);
        d[j]  = __ldg(dst + e);
        wt[j] = __ldg(w + e);
    }

    float4 a[EPW];
    #pragma unroll
    for (int j = 0; j < EPW; j++)
        a[j] = *reinterpret_cast<const float4*>(g_P + s[j] * NC + lane * 4);

    int4 cur[EPW];
    #pragma unroll
    for (int j = 0; j < EPW; j++)
        cur[j] = __ldcg(reinterpret_cast<const int4*>(g_keys + d[j] * H + lane * 4));

    #pragma unroll
    for (int j = 0; j < EPW; j++) {
        if (e0 + j >= E) break;
        int k0 = encf(fmaf(wt[j], vv.x, a[j].x));
        int k1 = encf(fmaf(wt[j], vv.y, a[j].y));
        int k2 = encf(fmaf(wt[j], vv.z, a[j].z));
        int k3 = encf(fmaf(wt[j], vv.w, a[j].w));
        int* kp = g_keys + d[j] * H + lane * 4;
        if (cur[j].x < k0) atomicMax(kp + 0, k0);
        if (cur[j].y < k1) atomicMax(kp + 1, k1);
        if (cur[j].z < k2) atomicMax(kp + 2, k2);
        if (cur[j].w < k3) atomicMax(kp + 3, k3);
    }
}

// ---------------------------------------------------------------------------
// GEMM2: out[M,128] = agg[M,128] @ Wu2[128,128] + C + b_upd
// agg decoded on the fly: key==KMIN -> 0 else dec(key)+T. Double-buffered.
// ---------------------------------------------------------------------------
__device__ __forceinline__ float4 load_agg4(int row, int kc) {
    int4   kv = *reinterpret_cast<const int4*>(g_keys + row * H + kc);
    float4 t4 = *reinterpret_cast<const float4*>(g_P + row * NC + H + kc);
    float4 a;
    a.x = (kv.x == KMIN) ? 0.f : decf(kv.x) + t4.x;
    a.y = (kv.y == KMIN) ? 0.f : decf(kv.y) + t4.y;
    a.z = (kv.z == KMIN) ? 0.f : decf(kv.z) + t4.z;
    a.w = (kv.w == KMIN) ? 0.f : decf(kv.w) + t4.w;
    return a;
}

__global__ __launch_bounds__(256, 2)
void gemm2_kernel(const float* __restrict__ Wupd,
                  const float* __restrict__ bupd,
                  float* __restrict__ out, int M) {
    __shared__ float As[2][8][128];
    __shared__ float Bs[2][8][128];
    const int bm = blockIdx.x * 128;
    const int tid = threadIdx.x;
    const int tx = tid & 15, ty = tid >> 4;
    const int arow = tid >> 1, acol = (tid & 1) * 4;
    const int brow = tid >> 5, bcol = (tid & 31) * 4;
    const bool arow_ok = (bm + arow < M);
    float acc[8][8] = {};

    {
        float4 a = make_float4(0.f, 0.f, 0.f, 0.f);
        if (arow_ok) a = load_agg4(bm + arow, acol);
        As[0][acol + 0][arow] = a.x; As[0][acol + 1][arow] = a.y;
        As[0][acol + 2][arow] = a.z; As[0][acol + 3][arow] = a.w;
        float4 bv = *reinterpret_cast<const float4*>(Wupd + (H + brow) * H + bcol);
        *reinterpret_cast<float4*>(&Bs[0][brow][bcol]) = bv;
    }
    __syncthreads();

    #pragma unroll 2
    for (int it = 0; it < 16; it++) {
        const int cur = it & 1;
        float4 av2 = make_float4(0.f, 0.f, 0.f, 0.f), bv2;
        if (it < 15) {
            int k0 = (it + 1) * 8;
            if (arow_ok) av2 = load_agg4(bm + arow, k0 + acol);
            bv2 = *reinterpret_cast<const float4*>(Wupd + (H + k0 + brow) * H + bcol);
        }

        #pragma unroll
        for (int kk = 0; kk < 8; kk++) {
            float4 a0 = *reinterpret_cast<const float4*>(&As[cur][kk][ty * 4]);
            float4 a1 = *reinterpret_cast<const float4*>(&As[cur][kk][64 + ty * 4]);
            float4 b0 = *reinterpret_cast<const float4*>(&Bs[cur][kk][tx * 4]);
            float4 b1 = *reinterpret_cast<const float4*>(&Bs[cur][kk][64 + tx * 4]);
            float a_[8] = {a0.x, a0.y, a0.z, a0.w, a1.x, a1.y, a1.z, a1.w};
            float b_[8] = {b0.x, b0.y, b0.z, b0.w, b1.x, b1.y, b1.z, b1.w};
            #pragma unroll
            for (int i = 0; i < 8; i++)
                #pragma unroll
                for (int j = 0; j < 8; j++)
                    acc[i][j] = fmaf(a_[i], b_[j], acc[i][j]);
        }

        if (it < 15) {
            const int nxt = cur ^ 1;
            As[nxt][acol + 0][arow] = av2.x; As[nxt][acol + 1][arow] = av2.y;
            As[nxt][acol + 2][arow] = av2.z; As[nxt][acol + 3][arow] = av2.w;
            *reinterpret_cast<float4*>(&Bs[nxt][brow][bcol]) = bv2;
        }
        __syncthreads();
    }

    #pragma unroll
    for (int i = 0; i < 8; i++) {
        int row = bm + ((i < 4) ? (ty * 4 + i) : (64 + ty * 4 + i - 4));
        if (row >= M) continue;
        #pragma unroll
        for (int j = 0; j < 8; j++) {
            int col = (j < 4) ? (tx * 4 + j) : (64 + tx * 4 + j - 4);
            out[row * H + col] = acc[i][j] + g_P[row * NC + 2 * H + col] + bupd[col];
        }
    }
}

// ---------------------------------------------------------------------------
extern "C" void kernel_launch(void* const* d_in, const int* in_sizes, int n_in,
                              void* d_out, int out_size) {
    const float* z    = (const float*)d_in[0];
    const int*   src  = (const int*)  d_in[1];
    const int*   dst  = (const int*)  d_in[2];
    const float* w    = (const float*)d_in[3];
    const float* Wmsg = (const float*)d_in[4];
    const float* bmsg = (const float*)d_in[5];
    const float* Wupd = (const float*)d_in[6];
    const float* bupd = (const float*)d_in[7];
    float* out = (float*)d_out;

    int n = in_sizes[0] / H;     // 50000
    int E = in_sizes[1];         // 640000

    pack_kernel<<<(H * NC + 255) / 256, 256>>>(Wmsg, Wupd);
    init_keys<<<1250, 256>>>(n * H / 4);
    gemm1_kernel<<<dim3((n + 127) / 128, NC / 128), 256>>>(z, bmsg, n);
    int warps = (E + EPW - 1) / EPW;
    edge_kernel<<<(warps * 32 + 255) / 256, 256>>>(src, dst, w, E);
    gemm2_kernel<<<(n + 127) / 128, 256>>>(Wupd, bupd, out, n);
}

// round 7
// speedup vs baseline: 1.5134x; 1.2454x over previous
#include <cuda_runtime.h>
#include <cstdint>

#define H     128
#define MAXN  50000
#define NC    384
#define EPW   4
#define KMIN  ((int)0x80000000)

#define BK      64
#define LDS_S   68               // smem row stride (floats); 68 % 32 == 4 -> conflict-free frags
#define TILE_F  (128 * LDS_S)    // floats per smem tile
#define SMEM_BYTES (2 * TILE_F * 4)

// ---- scratch (static device memory) ----
__device__ __align__(16) float g_Bt[NC * H];     // GEMM1 B^T: [n][k]
__device__ __align__(16) float g_Bu[H * H];      // GEMM2 B^T: Wu2^T [n][k]
__device__ __align__(16) float g_v[H];           // W_msg row 256
__device__ __align__(16) float g_P[MAXN * NC];   // per-node [A | T | C]
__device__ __align__(16) int   g_keys[MAXN * H]; // encoded running max

__device__ __forceinline__ int encf(float x) {
    int i = __float_as_int(x);
    return i >= 0 ? i : (i ^ 0x7FFFFFFF);
}
__device__ __forceinline__ float decf(int k) {
    int i = k >= 0 ? k : (k ^ 0x7FFFFFFF);
    return __int_as_float(i);
}
__device__ __forceinline__ uint32_t f2tf(float x) {
    uint32_t r;
    asm("cvt.rna.tf32.f32 %0, %1;" : "=r"(r) : "f"(x));
    return r;
}
__device__ __forceinline__ void mma_tf32(float* acc, uint32_t a0, uint32_t a1,
                                         uint32_t a2, uint32_t a3,
                                         uint32_t b0, uint32_t b1) {
    asm volatile(
        "mma.sync.aligned.m16n8k8.row.col.f32.tf32.tf32.f32 "
        "{%0,%1,%2,%3}, {%4,%5,%6,%7}, {%8,%9}, {%0,%1,%2,%3};"
        : "+f"(acc[0]), "+f"(acc[1]), "+f"(acc[2]), "+f"(acc[3])
        : "r"(a0), "r"(a1), "r"(a2), "r"(a3), "r"(b0), "r"(b1));
}

// ---------------------------------------------------------------------------
// Pack: g_Bt[n][k] = Wcat[k][n]; g_Bu[n][k] = Wupd[H+k][n]; g_v.
// ---------------------------------------------------------------------------
__global__ void pack_kernel(const float* __restrict__ Wmsg,
                            const float* __restrict__ Wupd) {
    int idx = blockIdx.x * blockDim.x + threadIdx.x;
    if (idx < H) g_v[idx] = Wmsg[256 * H + idx];
    if (idx < NC * H) {
        int n = idx / H, k = idx % H;
        float val;
        if (n < H)            val = Wmsg[k * H + n];
        else if (n < 2 * H)   val = Wmsg[(H + k) * H + (n - H)];
        else                  val = Wupd[k * H + (n - 2 * H)];
        g_Bt[idx] = val;
    } else if (idx < NC * H + H * H) {
        int j = idx - NC * H;
        int n = j / H, k = j % H;
        g_Bu[j] = Wupd[(H + k) * H + n];
    }
}

__global__ void init_keys(int total4) {
    int4 v = make_int4(KMIN, KMIN, KMIN, KMIN);
    int4* p = reinterpret_cast<int4*>(g_keys);
    int stride = gridDim.x * blockDim.x;
    for (int i = blockIdx.x * blockDim.x + threadIdx.x; i < total4; i += stride)
        p[i] = v;
}

// ---------------------------------------------------------------------------
// smem tile store helper: row-major [128][LDS_S], tf32-converted float4
// ---------------------------------------------------------------------------
__device__ __forceinline__ void st_tile4(float* sm, int row, int col, float4 v) {
    float* p = sm + row * LDS_S + col;
    p[0] = __uint_as_float(f2tf(v.x));
    p[1] = __uint_as_float(f2tf(v.y));
    p[2] = __uint_as_float(f2tf(v.z));
    p[3] = __uint_as_float(f2tf(v.w));
}

// ---------------------------------------------------------------------------
// mma compute core: 8 warps (2x4), warp tile 64x32, one BK=64 chunk.
// As: [128 rows][BK], Bs: [128 n][BK] (both stride LDS_S).
// ---------------------------------------------------------------------------
__device__ __forceinline__ void mma_chunk(const float* As, const float* Bs,
                                          float acc[4][4][4], int wm, int wn, int lane) {
    const int qr = lane >> 2, qk = lane & 3;
    #pragma unroll
    for (int ks = 0; ks < BK / 8; ks++) {
        uint32_t a[4][4], b[4][2];
        #pragma unroll
        for (int mt = 0; mt < 4; mt++) {
            const float* p = As + (wm * 64 + mt * 16 + qr) * LDS_S + ks * 8 + qk;
            a[mt][0] = __float_as_uint(p[0]);
            a[mt][1] = __float_as_uint(p[8 * LDS_S]);
            a[mt][2] = __float_as_uint(p[4]);
            a[mt][3] = __float_as_uint(p[8 * LDS_S + 4]);
        }
        #pragma unroll
        for (int nt = 0; nt < 4; nt++) {
            const float* p = Bs + (wn * 32 + nt * 8 + qr) * LDS_S + ks * 8 + qk;
            b[nt][0] = __float_as_uint(p[0]);
            b[nt][1] = __float_as_uint(p[4]);
        }
        #pragma unroll
        for (int mt = 0; mt < 4; mt++)
            #pragma unroll
            for (int nt = 0; nt < 4; nt++)
                mma_tf32(acc[mt][nt], a[mt][0], a[mt][1], a[mt][2], a[mt][3],
                         b[nt][0], b[nt][1]);
    }
}

// ---------------------------------------------------------------------------
// GEMM1 (mma tf32): P[:,bn:bn+128] = z @ Wcat[:,bn:] ; +b_msg on T cols.
// ---------------------------------------------------------------------------
__global__ void __launch_bounds__(256, 2)
gemm1_mma(const float* __restrict__ z, const float* __restrict__ bmsg, int M) {
    extern __shared__ float sm[];
    float* As = sm;
    float* Bs = sm + TILE_F;
    const int tid = threadIdx.x, wid = tid >> 5, lane = tid & 31;
    const int wm = wid >> 2, wn = wid & 3;
    const int bm = blockIdx.x * 128, bn = blockIdx.y * 128;
    const int lrow = tid >> 1, lhalf = tid & 1;
    float acc[4][4][4] = {};

    for (int c = 0; c < 2; c++) {
        int k0 = c * BK;
        #pragma unroll
        for (int i = 0; i < 8; i++) {
            int col = lhalf * 4 + i * 8;
            float4 av = make_float4(0.f, 0.f, 0.f, 0.f);
            if (bm + lrow < M)
                av = *reinterpret_cast<const float4*>(z + (bm + lrow) * H + k0 + col);
            st_tile4(As, lrow, col, av);
            float4 bv = *reinterpret_cast<const float4*>(g_Bt + (bn + lrow) * H + k0 + col);
            st_tile4(Bs, lrow, col, bv);
        }
        __syncthreads();
        mma_chunk(As, Bs, acc, wm, wn, lane);
        __syncthreads();
    }

    const int qr = lane >> 2, qk = lane & 3;
    const bool addb = (blockIdx.y == 1);
    #pragma unroll
    for (int mt = 0; mt < 4; mt++) {
        #pragma unroll
        for (int nt = 0; nt < 4; nt++) {
            int col = bn + wn * 32 + nt * 8 + qk * 2;
            float bx = 0.f, by = 0.f;
            if (addb) { bx = bmsg[col - H]; by = bmsg[col - H + 1]; }
            int r0 = bm + wm * 64 + mt * 16 + qr;
            if (r0 < M) {
                float2 v = make_float2(acc[mt][nt][0] + bx, acc[mt][nt][1] + by);
                *reinterpret_cast<float2*>(g_P + r0 * NC + col) = v;
            }
            int r1 = r0 + 8;
            if (r1 < M) {
                float2 v = make_float2(acc[mt][nt][2] + bx, acc[mt][nt][3] + by);
                *reinterpret_cast<float2*>(g_P + r1 * NC + col) = v;
            }
        }
    }
}

// ---------------------------------------------------------------------------
// Edge kernel: EPW edges/warp, racy __ldcg filter + atomicMax (exact).
// ---------------------------------------------------------------------------
__global__ void edge_kernel(const int* __restrict__ src,
                            const int* __restrict__ dst,
                            const float* __restrict__ w, int E) {
    int warp = (blockIdx.x * blockDim.x + threadIdx.x) >> 5;
    int lane = threadIdx.x & 31;
    int e0 = warp * EPW;
    if (e0 >= E) return;

    float4 vv = *reinterpret_cast<const float4*>(g_v + lane * 4);

    int s[EPW], d[EPW]; float wt[EPW];
    #pragma unroll
    for (int j = 0; j < EPW; j++) {
        int e = (e0 + j < E) ? e0 + j : e0;
        s[j]  = __ldg(src + e);
        d[j]  = __ldg(dst + e);
        wt[j] = __ldg(w + e);
    }
    float4 a[EPW];
    #pragma unroll
    for (int j = 0; j < EPW; j++)
        a[j] = *reinterpret_cast<const float4*>(g_P + s[j] * NC + lane * 4);
    int4 cur[EPW];
    #pragma unroll
    for (int j = 0; j < EPW; j++)
        cur[j] = __ldcg(reinterpret_cast<const int4*>(g_keys + d[j] * H + lane * 4));

    #pragma unroll
    for (int j = 0; j < EPW; j++) {
        if (e0 + j >= E) break;
        int k0 = encf(fmaf(wt[j], vv.x, a[j].x));
        int k1 = encf(fmaf(wt[j], vv.y, a[j].y));
        int k2 = encf(fmaf(wt[j], vv.z, a[j].z));
        int k3 = encf(fmaf(wt[j], vv.w, a[j].w));
        int* kp = g_keys + d[j] * H + lane * 4;
        if (cur[j].x < k0) atomicMax(kp + 0, k0);
        if (cur[j].y < k1) atomicMax(kp + 1, k1);
        if (cur[j].z < k2) atomicMax(kp + 2, k2);
        if (cur[j].w < k3) atomicMax(kp + 3, k3);
    }
}

// ---------------------------------------------------------------------------
// GEMM2 (mma tf32): out = agg @ Wu2 + C + b_upd; agg decoded in A loader.
// ---------------------------------------------------------------------------
__device__ __forceinline__ float4 load_agg4(int row, int kc) {
    int4   kv = *reinterpret_cast<const int4*>(g_keys + row * H + kc);
    float4 t4 = *reinterpret_cast<const float4*>(g_P + row * NC + H + kc);
    float4 a;
    a.x = (kv.x == KMIN) ? 0.f : decf(kv.x) + t4.x;
    a.y = (kv.y == KMIN) ? 0.f : decf(kv.y) + t4.y;
    a.z = (kv.z == KMIN) ? 0.f : decf(kv.z) + t4.z;
    a.w = (kv.w == KMIN) ? 0.f : decf(kv.w) + t4.w;
    return a;
}

__global__ void __launch_bounds__(256, 2)
gemm2_mma(const float* __restrict__ bupd, float* __restrict__ out, int M) {
    extern __shared__ float sm[];
    float* As = sm;
    float* Bs = sm + TILE_F;
    const int tid = threadIdx.x, wid = tid >> 5, lane = tid & 31;
    const int wm = wid >> 2, wn = wid & 3;
    const int bm = blockIdx.x * 128;
    const int lrow = tid >> 1, lhalf = tid & 1;
    float acc[4][4][4] = {};

    for (int c = 0; c < 2; c++) {
        int k0 = c * BK;
        #pragma unroll
        for (int i = 0; i < 8; i++) {
            int col = lhalf * 4 + i * 8;
            float4 av = make_float4(0.f, 0.f, 0.f, 0.f);
            if (bm + lrow < M) av = load_agg4(bm + lrow, k0 + col);
            st_tile4(As, lrow, col, av);
            float4 bv = *reinterpret_cast<const float4*>(g_Bu + lrow * H + k0 + col);
            st_tile4(Bs, lrow, col, bv);
        }
        __syncthreads();
        mma_chunk(As, Bs, acc, wm, wn, lane);
        __syncthreads();
    }

    const int qr = lane >> 2, qk = lane & 3;
    #pragma unroll
    for (int mt = 0; mt < 4; mt++) {
        #pragma unroll
        for (int nt = 0; nt < 4; nt++) {
            int col = wn * 32 + nt * 8 + qk * 2;
            float bx = bupd[col], by = bupd[col + 1];
            int r0 = bm + wm * 64 + mt * 16 + qr;
            if (r0 < M) {
                float2 c2 = *reinterpret_cast<const float2*>(g_P + r0 * NC + 2 * H + col);
                float2 v = make_float2(acc[mt][nt][0] + c2.x + bx,
                                       acc[mt][nt][1] + c2.y + by);
                *reinterpret_cast<float2*>(out + r0 * H + col) = v;
            }
            int r1 = r0 + 8;
            if (r1 < M) {
                float2 c2 = *reinterpret_cast<const float2*>(g_P + r1 * NC + 2 * H + col);
                float2 v = make_float2(acc[mt][nt][2] + c2.x + bx,
                                       acc[mt][nt][3] + c2.y + by);
                *reinterpret_cast<float2*>(out + r1 * H + col) = v;
            }
        }
    }
}

// ---------------------------------------------------------------------------
extern "C" void kernel_launch(void* const* d_in, const int* in_sizes, int n_in,
                              void* d_out, int out_size) {
    const float* z    = (const float*)d_in[0];
    const int*   src  = (const int*)  d_in[1];
    const int*   dst  = (const int*)  d_in[2];
    const float* w    = (const float*)d_in[3];
    const float* Wmsg = (const float*)d_in[4];
    const float* bmsg = (const float*)d_in[5];
    const float* Wupd = (const float*)d_in[6];
    const float* bupd = (const float*)d_in[7];
    float* out = (float*)d_out;

    int n = in_sizes[0] / H;     // 50000
    int E = in_sizes[1];         // 640000

    static bool attr_done = false;
    if (!attr_done) {
        cudaFuncSetAttribute(gemm1_mma, cudaFuncAttributeMaxDynamicSharedMemorySize, SMEM_BYTES);
        cudaFuncSetAttribute(gemm2_mma, cudaFuncAttributeMaxDynamicSharedMemorySize, SMEM_BYTES);
        attr_done = true;
    }

    pack_kernel<<<(NC * H + H * H + 255) / 256, 256>>>(Wmsg, Wupd);
    init_keys<<<1250, 256>>>(n * H / 4);
    int nb = (n + 127) / 128;
    gemm1_mma<<<dim3(nb, 3), 256, SMEM_BYTES>>>(z, bmsg, n);
    int warps = (E + EPW - 1) / EPW;
    edge_kernel<<<(warps * 32 + 255) / 256, 256>>>(src, dst, w, E);
    gemm2_mma<<<nb, 256, SMEM_BYTES>>>(bupd, out, n);
}

// round 8
// speedup vs baseline: 1.9002x; 1.2556x over previous
#include <cuda_runtime.h>
#include <cstdint>

#define H     128
#define MAXN  50000
#define MAXE  640000
#define NC    384

#define BK      64
#define LDS_S   68               // smem row stride (floats); 68 % 32 == 4 -> conflict-free frags
#define TILE_F  (128 * LDS_S)
#define SMEM_BYTES (2 * TILE_F * 4)

// ---- scratch (static device memory) ----
__device__ __align__(16) float g_Bt[NC * H];     // GEMM1 B^T: [n][k]
__device__ __align__(16) float g_Bu[H * H];      // GEMM2 B^T: Wu2^T [n][k]
__device__ __align__(16) float g_v[H];           // W_msg weight column
__device__ __align__(16) float g_P[MAXN * NC];   // per-node [A | T | C]
__device__ __align__(16) float g_agg[MAXN * H];  // aggregated (max + T, or 0)
// CSR build
__device__ int   g_cnt[MAXN];
__device__ int   g_ro[MAXN];
__device__ int   g_cur[MAXN];
__device__ int   g_bsum[128];
__device__ int   g_boff[128];
__device__ int   g_es[MAXE];
__device__ float g_ew[MAXE];

__device__ __forceinline__ uint32_t f2tf(float x) {
    uint32_t r;
    asm("cvt.rna.tf32.f32 %0, %1;" : "=r"(r) : "f"(x));
    return r;
}
__device__ __forceinline__ void mma_tf32(float* acc, uint32_t a0, uint32_t a1,
                                         uint32_t a2, uint32_t a3,
                                         uint32_t b0, uint32_t b1) {
    asm volatile(
        "mma.sync.aligned.m16n8k8.row.col.f32.tf32.tf32.f32 "
        "{%0,%1,%2,%3}, {%4,%5,%6,%7}, {%8,%9}, {%0,%1,%2,%3};"
        : "+f"(acc[0]), "+f"(acc[1]), "+f"(acc[2]), "+f"(acc[3])
        : "r"(a0), "r"(a1), "r"(a2), "r"(a3), "r"(b0), "r"(b1));
}

// ---------------------------------------------------------------------------
// Pack weights (transposed for col-major B frags) + zero histogram counters.
// ---------------------------------------------------------------------------
__global__ void pack_kernel(const float* __restrict__ Wmsg,
                            const float* __restrict__ Wupd) {
    int idx = blockIdx.x * blockDim.x + threadIdx.x;
    if (idx < H) g_v[idx] = Wmsg[256 * H + idx];
    if (idx < MAXN) g_cnt[idx] = 0;
    if (idx < NC * H) {
        int n = idx / H, k = idx % H;
        float val;
        if (n < H)            val = Wmsg[k * H + n];
        else if (n < 2 * H)   val = Wmsg[(H + k) * H + (n - H)];
        else                  val = Wupd[k * H + (n - 2 * H)];
        g_Bt[idx] = val;
    } else if (idx < NC * H + H * H) {
        int j = idx - NC * H;
        int n = j / H, k = j % H;
        g_Bu[j] = Wupd[(H + k) * H + n];
    }
}

// ---------------------------------------------------------------------------
// CSR build: histogram -> scan(3 stages) -> scatter
// ---------------------------------------------------------------------------
__global__ void hist_kernel(const int* __restrict__ dst, int E) {
    int i = blockIdx.x * blockDim.x + threadIdx.x;
    if (i < E) atomicAdd(&g_cnt[dst[i]], 1);
}

__global__ void scan1_kernel(int n) {
    __shared__ int s[512];
    int t = threadIdx.x;
    int i = blockIdx.x * 512 + t;
    int v = (i < n) ? g_cnt[i] : 0;
    s[t] = v;
    __syncthreads();
    #pragma unroll
    for (int off = 1; off < 512; off <<= 1) {
        int u = (t >= off) ? s[t - off] : 0;
        __syncthreads();
        s[t] += u;
        __syncthreads();
    }
    if (i < n) g_ro[i] = s[t] - v;            // exclusive within block
    if (t == 511) g_bsum[blockIdx.x] = s[511];
}

__global__ void scan2_kernel(int nb) {
    if (threadIdx.x == 0) {
        int run = 0;
        for (int j = 0; j < nb; j++) { g_boff[j] = run; run += g_bsum[j]; }
    }
}

__global__ void scan3_kernel(int n) {
    int i = blockIdx.x * blockDim.x + threadIdx.x;
    if (i < n) {
        int v = g_ro[i] + g_boff[i >> 9];
        g_ro[i] = v;
        g_cur[i] = v;
    }
}

__global__ void scatter_kernel(const int* __restrict__ src,
                               const int* __restrict__ dst,
                               const float* __restrict__ w, int E) {
    int i = blockIdx.x * blockDim.x + threadIdx.x;
    if (i < E) {
        int d = dst[i];
        int p = atomicAdd(&g_cur[d], 1);
        g_es[p] = src[i];
        g_ew[p] = w[i];
    }
}

// ---------------------------------------------------------------------------
// Aggregate: one warp per node; register max over its CSR segment.
// agg[node] = (deg ? max_e(A[src_e] + w_e*v) + T[node] : 0)
// fp32 max is exactly associative -> order-independent, deterministic.
// ---------------------------------------------------------------------------
__global__ void __launch_bounds__(256)
aggregate_kernel(int n) {
    int node = (blockIdx.x * blockDim.x + threadIdx.x) >> 5;
    int lane = threadIdx.x & 31;
    if (node >= n) return;
    int start = g_ro[node];
    int deg   = g_cnt[node];

    float4 vv = *reinterpret_cast<const float4*>(g_v + lane * 4);
    const float NEGINF = __int_as_float(0xff800000);
    float4 m = make_float4(NEGINF, NEGINF, NEGINF, NEGINF);

    for (int e = 0; e < deg; e += 4) {
        int nb = deg - e; if (nb > 4) nb = 4;
        int   s4[4]; float w4[4];
        #pragma unroll
        for (int j = 0; j < 4; j++) {
            int idx = start + e + ((j < nb) ? j : 0);
            s4[j] = __ldg(g_es + idx);
            w4[j] = __ldg(g_ew + idx);
        }
        float4 a4[4];
        #pragma unroll
        for (int j = 0; j < 4; j++)
            a4[j] = *reinterpret_cast<const float4*>(g_P + s4[j] * NC + lane * 4);
        #pragma unroll
        for (int j = 0; j < 4; j++) {
            if (j < nb) {
                m.x = fmaxf(m.x, fmaf(w4[j], vv.x, a4[j].x));
                m.y = fmaxf(m.y, fmaf(w4[j], vv.y, a4[j].y));
                m.z = fmaxf(m.z, fmaf(w4[j], vv.z, a4[j].z));
                m.w = fmaxf(m.w, fmaf(w4[j], vv.w, a4[j].w));
            }
        }
    }

    float4 o = make_float4(0.f, 0.f, 0.f, 0.f);
    if (deg > 0) {
        float4 t4 = *reinterpret_cast<const float4*>(g_P + node * NC + H + lane * 4);
        o.x = m.x + t4.x; o.y = m.y + t4.y;
        o.z = m.z + t4.z; o.w = m.w + t4.w;
    }
    *reinterpret_cast<float4*>(g_agg + node * H + lane * 4) = o;
}

// ---------------------------------------------------------------------------
// smem tile store helper: row-major [128][LDS_S], tf32-converted float4
// ---------------------------------------------------------------------------
__device__ __forceinline__ void st_tile4(float* sm, int row, int col, float4 v) {
    float* p = sm + row * LDS_S + col;
    p[0] = __uint_as_float(f2tf(v.x));
    p[1] = __uint_as_float(f2tf(v.y));
    p[2] = __uint_as_float(f2tf(v.z));
    p[3] = __uint_as_float(f2tf(v.w));
}

// ---------------------------------------------------------------------------
// mma compute core: 8 warps (2x4), warp tile 64x32, one BK=64 chunk.
// ---------------------------------------------------------------------------
__device__ __forceinline__ void mma_chunk(const float* As, const float* Bs,
                                          float acc[4][4][4], int wm, int wn, int lane) {
    const int qr = lane >> 2, qk = lane & 3;
    #pragma unroll
    for (int ks = 0; ks < BK / 8; ks++) {
        uint32_t a[4][4], b[4][2];
        #pragma unroll
        for (int mt = 0; mt < 4; mt++) {
            const float* p = As + (wm * 64 + mt * 16 + qr) * LDS_S + ks * 8 + qk;
            a[mt][0] = __float_as_uint(p[0]);
            a[mt][1] = __float_as_uint(p[8 * LDS_S]);
            a[mt][2] = __float_as_uint(p[4]);
            a[mt][3] = __float_as_uint(p[8 * LDS_S + 4]);
        }
        #pragma unroll
        for (int nt = 0; nt < 4; nt++) {
            const float* p = Bs + (wn * 32 + nt * 8 + qr) * LDS_S + ks * 8 + qk;
            b[nt][0] = __float_as_uint(p[0]);
            b[nt][1] = __float_as_uint(p[4]);
        }
        #pragma unroll
        for (int mt = 0; mt < 4; mt++)
            #pragma unroll
            for (int nt = 0; nt < 4; nt++)
                mma_tf32(acc[mt][nt], a[mt][0], a[mt][1], a[mt][2], a[mt][3],
                         b[nt][0], b[nt][1]);
    }
}

// ---------------------------------------------------------------------------
// GEMM1 (mma tf32): P[:,bn:bn+128] = z @ Wcat[:,bn:] ; +b_msg on T cols.
// ---------------------------------------------------------------------------
__global__ void __launch_bounds__(256, 2)
gemm1_mma(const float* __restrict__ z, const float* __restrict__ bmsg, int M) {
    extern __shared__ float sm[];
    float* As = sm;
    float* Bs = sm + TILE_F;
    const int tid = threadIdx.x, wid = tid >> 5, lane = tid & 31;
    const int wm = wid >> 2, wn = wid & 3;
    const int bm = blockIdx.x * 128, bn = blockIdx.y * 128;
    const int lrow = tid >> 1, lhalf = tid & 1;
    float acc[4][4][4] = {};

    for (int c = 0; c < 2; c++) {
        int k0 = c * BK;
        #pragma unroll
        for (int i = 0; i < 8; i++) {
            int col = lhalf * 4 + i * 8;
            float4 av = make_float4(0.f, 0.f, 0.f, 0.f);
            if (bm + lrow < M)
                av = *reinterpret_cast<const float4*>(z + (bm + lrow) * H + k0 + col);
            st_tile4(As, lrow, col, av);
            float4 bv = *reinterpret_cast<const float4*>(g_Bt + (bn + lrow) * H + k0 + col);
            st_tile4(Bs, lrow, col, bv);
        }
        __syncthreads();
        mma_chunk(As, Bs, acc, wm, wn, lane);
        __syncthreads();
    }

    const int qr = lane >> 2, qk = lane & 3;
    const bool addb = (blockIdx.y == 1);
    #pragma unroll
    for (int mt = 0; mt < 4; mt++) {
        #pragma unroll
        for (int nt = 0; nt < 4; nt++) {
            int col = bn + wn * 32 + nt * 8 + qk * 2;
            float bx = 0.f, by = 0.f;
            if (addb) { bx = bmsg[col - H]; by = bmsg[col - H + 1]; }
            int r0 = bm + wm * 64 + mt * 16 + qr;
            if (r0 < M) {
                float2 v = make_float2(acc[mt][nt][0] + bx, acc[mt][nt][1] + by);
                *reinterpret_cast<float2*>(g_P + r0 * NC + col) = v;
            }
            int r1 = r0 + 8;
            if (r1 < M) {
                float2 v = make_float2(acc[mt][nt][2] + bx, acc[mt][nt][3] + by);
                *reinterpret_cast<float2*>(g_P + r1 * NC + col) = v;
            }
        }
    }
}

// ---------------------------------------------------------------------------
// GEMM2 (mma tf32): out = agg @ Wu2 + C + b_upd; A = g_agg (plain float4).
// ---------------------------------------------------------------------------
__global__ void __launch_bounds__(256, 2)
gemm2_mma(const float* __restrict__ bupd, float* __restrict__ out, int M) {
    extern __shared__ float sm[];
    float* As = sm;
    float* Bs = sm + TILE_F;
    const int tid = threadIdx.x, wid = tid >> 5, lane = tid & 31;
    const int wm = wid >> 2, wn = wid & 3;
    const int bm = blockIdx.x * 128;
    const int lrow = tid >> 1, lhalf = tid & 1;
    float acc[4][4][4] = {};

    for (int c = 0; c < 2; c++) {
        int k0 = c * BK;
        #pragma unroll
        for (int i = 0; i < 8; i++) {
            int col = lhalf * 4 + i * 8;
            float4 av = make_float4(0.f, 0.f, 0.f, 0.f);
            if (bm + lrow < M)
                av = *reinterpret_cast<const float4*>(g_agg + (bm + lrow) * H + k0 + col);
            st_tile4(As, lrow, col, av);
            float4 bv = *reinterpret_cast<const float4*>(g_Bu + lrow * H + k0 + col);
            st_tile4(Bs, lrow, col, bv);
        }
        __syncthreads();
        mma_chunk(As, Bs, acc, wm, wn, lane);
        __syncthreads();
    }

    const int qr = lane >> 2, qk = lane & 3;
    #pragma unroll
    for (int mt = 0; mt < 4; mt++) {
        #pragma unroll
        for (int nt = 0; nt < 4; nt++) {
            int col = wn * 32 + nt * 8 + qk * 2;
            float bx = bupd[col], by = bupd[col + 1];
            int r0 = bm + wm * 64 + mt * 16 + qr;
            if (r0 < M) {
                float2 c2 = *reinterpret_cast<const float2*>(g_P + r0 * NC + 2 * H + col);
                float2 v = make_float2(acc[mt][nt][0] + c2.x + bx,
                                       acc[mt][nt][1] + c2.y + by);
                *reinterpret_cast<float2*>(out + r0 * H + col) = v;
            }
            int r1 = r0 + 8;
            if (r1 < M) {
                float2 c2 = *reinterpret_cast<const float2*>(g_P + r1 * NC + 2 * H + col);
                float2 v = make_float2(acc[mt][nt][2] + c2.x + bx,
                                       acc[mt][nt][3] + c2.y + by);
                *reinterpret_cast<float2*>(out + r1 * H + col) = v;
            }
        }
    }
}

// ---------------------------------------------------------------------------
extern "C" void kernel_launch(void* const* d_in, const int* in_sizes, int n_in,
                              void* d_out, int out_size) {
    const float* z    = (const float*)d_in[0];
    const int*   src  = (const int*)  d_in[1];
    const int*   dst  = (const int*)  d_in[2];
    const float* w    = (const float*)d_in[3];
    const float* Wmsg = (const float*)d_in[4];
    const float* bmsg = (const float*)d_in[5];
    const float* Wupd = (const float*)d_in[6];
    const float* bupd = (const float*)d_in[7];
    float* out = (float*)d_out;

    int n = in_sizes[0] / H;     // 50000
    int E = in_sizes[1];         // 640000

    static bool attr_done = false;
    if (!attr_done) {
        cudaFuncSetAttribute(gemm1_mma, cudaFuncAttributeMaxDynamicSharedMemorySize, SMEM_BYTES);
        cudaFuncSetAttribute(gemm2_mma, cudaFuncAttributeMaxDynamicSharedMemorySize, SMEM_BYTES);
        attr_done = true;
    }

    int nb_scan = (n + 511) / 512;
    int nbk = (n + 127) / 128;

    pack_kernel<<<256, 256>>>(Wmsg, Wupd);
    hist_kernel<<<(E + 255) / 256, 256>>>(dst, E);
    scan1_kernel<<<nb_scan, 512>>>(n);
    scan2_kernel<<<1, 32>>>(nb_scan);
    scan3_kernel<<<(n + 255) / 256, 256>>>(n);
    scatter_kernel<<<(E + 255) / 256, 256>>>(src, dst, w, E);
    gemm1_mma<<<dim3(nbk, 3), 256, SMEM_BYTES>>>(z, bmsg, n);
    aggregate_kernel<<<(n * 32 + 255) / 256, 256>>>(n);
    gemm2_mma<<<nbk, 256, SMEM_BYTES>>>(bupd, out, n);
}